// round 1
// baseline (speedup 1.0000x reference)
#include <cuda_runtime.h>
#include <cuda_bf16.h>

#define N_TASK 50000
#define N_RET  20000
#define N_DRAM 5000
#define N_LINKN 100000
#define E_RET  1000000
#define E_DRAM 250000
#define E_LINK 2000000
#define HD 64

// ---------------- device scratch (no allocations allowed) ----------------
__device__ float    g_s_ret[N_RET];
__device__ float    g_s_dram[N_DRAM];
__device__ float    g_s_link[N_LINKN];
__device__ unsigned g_smax[3 * N_TASK];
__device__ unsigned g_smin[3 * N_TASK];
__device__ float    g_h_task[N_TASK * HD];
__device__ int      g_cnt[N_LINKN];
__device__ int      g_offs[N_LINKN];
__device__ int      g_cursor[N_LINKN];
__device__ int      g_csr[E_LINK];

// order-preserving float<->uint encoding (all real floats encode > 0)
__device__ __forceinline__ unsigned encf(float f) {
    unsigned u = __float_as_uint(f);
    return (u & 0x80000000u) ? ~u : (u | 0x80000000u);
}
__device__ __forceinline__ float decf(unsigned u) {
    return __uint_as_float((u & 0x80000000u) ? (u & 0x7FFFFFFFu) : ~u);
}

// ---------------- init ----------------
__global__ void k_init() {
    int i = blockIdx.x * blockDim.x + threadIdx.x;
    if (i < N_RET)  g_s_ret[i]  = 0.f;
    if (i < N_DRAM) g_s_dram[i] = 0.f;
    if (i < N_LINKN) { g_s_link[i] = 0.f; g_cnt[i] = 0; }
    if (i < N_TASK) {
#pragma unroll
        for (int et = 0; et < 3; et++) {
            g_smax[et * N_TASK + i] = 0u;
            g_smin[et * N_TASK + i] = 0xFFFFFFFFu;
        }
    }
}

// ---------------- scalar segment sum: s[mod[e]] += feat[e] ----------------
__global__ void k_segsum(const float* __restrict__ feat,
                         const int* __restrict__ mod,
                         int which, int E) {
    int e = blockIdx.x * blockDim.x + threadIdx.x;
    if (e >= E) return;
    float* s = (which == 0) ? g_s_ret : (which == 1) ? g_s_dram : g_s_link;
    atomicAdd(&s[mod[e]], feat[e]);
}

// ---------------- per-task scalar max/min over edges (+ link histogram) ----
__global__ void k_minmax(const int* __restrict__ mod,
                         const int* __restrict__ task,
                         int which, int E, int do_cnt) {
    int e = blockIdx.x * blockDim.x + threadIdx.x;
    if (e >= E) return;
    const float* s = (which == 0) ? g_s_ret : (which == 1) ? g_s_dram : g_s_link;
    int m = mod[e];
    unsigned k = encf(s[m]);
    int t = task[e];
    atomicMax(&g_smax[which * N_TASK + t], k);
    atomicMin(&g_smin[which * N_TASK + t], k);
    if (do_cnt) atomicAdd(&g_cnt[m], 1);
}

// ---------------- single-block exclusive scan of g_cnt -> g_offs/g_cursor --
__global__ void k_scan() {
    const int T = 1024;
    const int CH = (N_LINKN + T - 1) / T;  // 98
    __shared__ int sh[T];
    int tid = threadIdx.x;
    int base = tid * CH;
    int s = 0;
    for (int j = 0; j < CH; j++) {
        int i = base + j;
        if (i < N_LINKN) s += g_cnt[i];
    }
    sh[tid] = s;
    __syncthreads();
    for (int off = 1; off < T; off <<= 1) {
        int v = (tid >= off) ? sh[tid - off] : 0;
        __syncthreads();
        sh[tid] += v;
        __syncthreads();
    }
    int run = sh[tid] - s;  // exclusive prefix for this thread's chunk
    for (int j = 0; j < CH; j++) {
        int i = base + j;
        if (i < N_LINKN) {
            g_offs[i] = run;
            g_cursor[i] = run;
            run += g_cnt[i];
        }
    }
}

// ---------------- CSR scatter: csr[pos] = task_link[e] --------------------
__global__ void k_scatter(const int* __restrict__ mod,
                          const int* __restrict__ task) {
    int e = blockIdx.x * blockDim.x + threadIdx.x;
    if (e >= E_LINK) return;
    int p = atomicAdd(&g_cursor[mod[e]], 1);
    g_csr[p] = task[e];
}

// ---------------- task update: v[192] -> tanh(v @ Wtask^T + b) -----------
// block = 256 threads, tile = 64 tasks x 64 h, K = 192
__global__ void k_task(const float* __restrict__ Wret,  const float* __restrict__ bret,
                       const float* __restrict__ Wdram, const float* __restrict__ bdram,
                       const float* __restrict__ Wlink, const float* __restrict__ blink,
                       const float* __restrict__ Wtask, const float* __restrict__ btask) {
    extern __shared__ float sh[];
    float* sV  = sh;               // [64][192]
    float* sWt = sh + 64 * 192;    // [192][66]  (padded)

    int tb = blockIdx.x * 64;

    // load Wtask transposed into shared: sWt[k][h] = Wtask[h*192 + k]
    for (int idx = threadIdx.x; idx < 64 * 192; idx += 256) {
        int h = idx / 192, k = idx - h * 192;
        sWt[k * 66 + h] = Wtask[idx];
    }

    // build v: v[t][k] with k = et*64 + h, via monotone max/min trick
    for (int idx = threadIdx.x; idx < 64 * 192; idx += 256) {
        int tl = idx / 192, k = idx - tl * 192;
        int et = k >> 6, h = k & 63;
        int t = tb + tl;
        float v = 0.f;
        if (t < N_TASK) {
            unsigned mk = g_smax[et * N_TASK + t];
            if (mk != 0u) {  // task has >=1 edge of this etype
                const float* We = (et == 0) ? Wret : (et == 1) ? Wdram : Wlink;
                const float* be = (et == 0) ? bret : (et == 1) ? bdram : blink;
                float w = We[h];
                float sv = (w >= 0.f) ? decf(mk) : decf(g_smin[et * N_TASK + t]);
                v = tanhf(fmaf(w, sv, be[h]));
            }
        }
        sV[idx] = v;
    }
    __syncthreads();

    int tx = threadIdx.x & 31, ty = threadIdx.x >> 5;
    int h0 = tx * 2;       // two output columns
    int t0 = ty * 8;       // eight tasks
    float acc0[8], acc1[8];
#pragma unroll
    for (int i = 0; i < 8; i++) { acc0[i] = 0.f; acc1[i] = 0.f; }

    const float* vb = sV + t0 * 192;
    for (int k = 0; k < 192; k += 4) {
        float2 w0 = *(const float2*)(sWt + (k + 0) * 66 + h0);
        float2 w1 = *(const float2*)(sWt + (k + 1) * 66 + h0);
        float2 w2 = *(const float2*)(sWt + (k + 2) * 66 + h0);
        float2 w3 = *(const float2*)(sWt + (k + 3) * 66 + h0);
#pragma unroll
        for (int i = 0; i < 8; i++) {
            float4 v = *(const float4*)(vb + i * 192 + k);
            acc0[i] = fmaf(v.x, w0.x, acc0[i]); acc1[i] = fmaf(v.x, w0.y, acc1[i]);
            acc0[i] = fmaf(v.y, w1.x, acc0[i]); acc1[i] = fmaf(v.y, w1.y, acc1[i]);
            acc0[i] = fmaf(v.z, w2.x, acc0[i]); acc1[i] = fmaf(v.z, w2.y, acc1[i]);
            acc0[i] = fmaf(v.w, w3.x, acc0[i]); acc1[i] = fmaf(v.w, w3.y, acc1[i]);
        }
    }

    float b0 = btask[h0], b1 = btask[h0 + 1];
#pragma unroll
    for (int i = 0; i < 8; i++) {
        int t = tb + t0 + i;
        if (t < N_TASK) {
            float2 o;
            o.x = tanhf(acc0[i] + b0);
            o.y = tanhf(acc1[i] + b1);
            *(float2*)&g_h_task[t * 64 + h0] = o;
        }
    }
}

// ---------------- link mean: warp per link node, CSR gather ---------------
__global__ void k_linkmean(float* __restrict__ out) {
    int gw = (blockIdx.x * blockDim.x + threadIdx.x) >> 5;
    if (gw >= N_LINKN) return;
    int lane = threadIdx.x & 31;
    int beg = g_offs[gw];
    int n = g_cnt[gw];
    float ax = 0.f, ay = 0.f;
    int j = 0;
    for (; j + 1 < n; j += 2) {  // unroll-2 for MLP
        int t0g = g_csr[beg + j];
        int t1g = g_csr[beg + j + 1];
        float2 v0 = *(const float2*)&g_h_task[t0g * 64 + lane * 2];
        float2 v1 = *(const float2*)&g_h_task[t1g * 64 + lane * 2];
        ax += v0.x + v1.x;
        ay += v0.y + v1.y;
    }
    if (j < n) {
        int t = g_csr[beg + j];
        float2 v = *(const float2*)&g_h_task[t * 64 + lane * 2];
        ax += v.x;
        ay += v.y;
    }
    float inv = (n > 0) ? 1.0f / (float)n : 0.f;
    float2 o;
    o.x = ax * inv;
    o.y = ay * inv;
    *(float2*)&out[(size_t)gw * 64 + lane * 2] = o;
}

// ---------------- launch ----------------
extern "C" void kernel_launch(void* const* d_in, const int* in_sizes, int n_in,
                              void* d_out, int out_size) {
    const float* feat_ret  = (const float*)d_in[0];
    const float* feat_dram = (const float*)d_in[1];
    const float* feat_link = (const float*)d_in[2];
    const float* W_ret   = (const float*)d_in[3];
    const float* b_ret   = (const float*)d_in[4];
    const float* W_dram  = (const float*)d_in[5];
    const float* b_dram  = (const float*)d_in[6];
    const float* W_link  = (const float*)d_in[7];
    const float* b_link  = (const float*)d_in[8];
    const float* W_task  = (const float*)d_in[9];
    const float* b_task  = (const float*)d_in[10];
    const int* task_ret  = (const int*)d_in[11];
    const int* mod_ret   = (const int*)d_in[12];
    const int* task_dram = (const int*)d_in[13];
    const int* mod_dram  = (const int*)d_in[14];
    const int* task_link = (const int*)d_in[15];
    const int* mod_link  = (const int*)d_in[16];
    float* out = (float*)d_out;

    const int TPB = 256;
    const int smem_task = (64 * 192 + 192 * 66) * (int)sizeof(float);  // 99840 B
    cudaFuncSetAttribute(k_task, cudaFuncAttributeMaxDynamicSharedMemorySize, smem_task);

    k_init<<<(N_LINKN + TPB - 1) / TPB, TPB>>>();

    k_segsum<<<(E_RET  + TPB - 1) / TPB, TPB>>>(feat_ret,  mod_ret,  0, E_RET);
    k_segsum<<<(E_DRAM + TPB - 1) / TPB, TPB>>>(feat_dram, mod_dram, 1, E_DRAM);
    k_segsum<<<(E_LINK + TPB - 1) / TPB, TPB>>>(feat_link, mod_link, 2, E_LINK);

    k_minmax<<<(E_RET  + TPB - 1) / TPB, TPB>>>(mod_ret,  task_ret,  0, E_RET,  0);
    k_minmax<<<(E_DRAM + TPB - 1) / TPB, TPB>>>(mod_dram, task_dram, 1, E_DRAM, 0);
    k_minmax<<<(E_LINK + TPB - 1) / TPB, TPB>>>(mod_link, task_link, 2, E_LINK, 1);

    k_scan<<<1, 1024>>>();
    k_scatter<<<(E_LINK + TPB - 1) / TPB, TPB>>>(mod_link, task_link);

    k_task<<<(N_TASK + 63) / 64, TPB, smem_task>>>(W_ret, b_ret, W_dram, b_dram,
                                                   W_link, b_link, W_task, b_task);

    k_linkmean<<<(N_LINKN * 32 + TPB - 1) / TPB, TPB>>>(out);
}